// round 1
// baseline (speedup 1.0000x reference)
#include <cuda_runtime.h>
#include <math.h>

#define BT_   16
#define SEQ   512
#define EDIM  768
#define NH    12
#define HD    64
#define QKV3  2304
#define MROWS (BT_*SEQ)   /* 8192 */

// Scratch (allocation-free): qkv projection output and attention output.
__device__ float g_qkv[(size_t)MROWS * QKV3];   // ~75.5 MB
__device__ float g_attn[(size_t)MROWS * EDIM];  // ~25 MB

// ---------------------------------------------------------------------------
// SGEMM + bias: C[M,N] = A[M,K] @ B[K,N] + bias[N]
// 128x128 block tile, BK=16, 256 threads, 8x8 microtile per thread.
// M,N multiples of 128; K multiple of 16 (true for all three calls).
// ---------------------------------------------------------------------------
__global__ __launch_bounds__(256)
void sgemm_bias(const float* __restrict__ A, const float* __restrict__ B,
                const float* __restrict__ bias, float* __restrict__ C,
                int M, int N, int K)
{
    __shared__ float As[16][128];
    __shared__ float Bs[16][128];

    const int t   = threadIdx.x;
    const int bn0 = blockIdx.x * 128;
    const int bm0 = blockIdx.y * 128;
    const int tx  = t & 15;
    const int ty  = t >> 4;

    float acc[8][8];
    #pragma unroll
    for (int i = 0; i < 8; i++)
        #pragma unroll
        for (int j = 0; j < 8; j++) acc[i][j] = 0.f;

    for (int k0 = 0; k0 < K; k0 += 16) {
        // A tile: 128 rows x 16 cols -> store transposed As[k][m]
        #pragma unroll
        for (int l = 0; l < 2; l++) {
            int idx = t + l * 256;          // float4 index, 512 total
            int row = idx >> 2;
            int c4  = idx & 3;
            float4 v = *(const float4*)(A + (size_t)(bm0 + row) * K + k0 + c4 * 4);
            As[c4 * 4 + 0][row] = v.x;
            As[c4 * 4 + 1][row] = v.y;
            As[c4 * 4 + 2][row] = v.z;
            As[c4 * 4 + 3][row] = v.w;
        }
        // B tile: 16 rows x 128 cols
        #pragma unroll
        for (int l = 0; l < 2; l++) {
            int idx = t + l * 256;
            int row = idx >> 5;
            int c4  = idx & 31;
            *(float4*)(&Bs[row][c4 * 4]) =
                *(const float4*)(B + (size_t)(k0 + row) * N + bn0 + c4 * 4);
        }
        __syncthreads();

        #pragma unroll
        for (int kk = 0; kk < 16; kk++) {
            float a[8], b[8];
            *(float4*)(a)     = *(const float4*)(&As[kk][ty * 8]);
            *(float4*)(a + 4) = *(const float4*)(&As[kk][ty * 8 + 4]);
            *(float4*)(b)     = *(const float4*)(&Bs[kk][tx * 8]);
            *(float4*)(b + 4) = *(const float4*)(&Bs[kk][tx * 8 + 4]);
            #pragma unroll
            for (int i = 0; i < 8; i++)
                #pragma unroll
                for (int j = 0; j < 8; j++)
                    acc[i][j] += a[i] * b[j];
        }
        __syncthreads();
    }

    #pragma unroll
    for (int i = 0; i < 8; i++) {
        int r = bm0 + ty * 8 + i;
        #pragma unroll
        for (int j = 0; j < 8; j += 4) {
            int c = bn0 + tx * 8 + j;
            float4 v;
            v.x = acc[i][j]     + bias[c];
            v.y = acc[i][j + 1] + bias[c + 1];
            v.z = acc[i][j + 2] + bias[c + 2];
            v.w = acc[i][j + 3] + bias[c + 3];
            *(float4*)(C + (size_t)r * N + c) = v;
        }
    }
}

// ---------------------------------------------------------------------------
// Flash-style attention. Grid: (SEQ/128, NH, BT). 128 threads/block.
// Thread r owns q-row (q0 + r): Q in regs, O[64] accumulator in regs,
// online softmax over 16-wide column chunks.
// Dynamic smem layout (floats):
//   [0,4096)      Ks  [64][64]
//   [4096,8192)   Vs  [64][64]
//   [8192,16512)  Es  [128][65]   (edge+mask, pad 65 -> conflict-free col read)
//   Q staging reuses [0, 128*68) before the k-loop starts.
// ---------------------------------------------------------------------------
#define ATTN_SMEM_FLOATS 16512
#define ATTN_SMEM_BYTES  (ATTN_SMEM_FLOATS * 4)

__global__ __launch_bounds__(128)
void attn_kernel(const float* __restrict__ mask, const float* __restrict__ edge)
{
    extern __shared__ float sm[];
    float* Ks = sm;
    float* Vs = sm + 4096;
    float* Es = sm + 8192;

    const int r  = threadIdx.x;
    const int q0 = blockIdx.x * 128;
    const int h  = blockIdx.y;
    const int bt = blockIdx.z;

    const float* qkv_bt = g_qkv + (size_t)bt * SEQ * QKV3;

    // Stage Q tile (coalesced) into sm with stride 68, then copy to regs.
    {
        const float* qsrc = qkv_bt + (size_t)q0 * QKV3 + h * HD;
        #pragma unroll
        for (int i = r; i < 2048; i += 128) {       // 2048 float4s
            int row = i >> 4;
            int c4  = i & 15;
            float4 v = *(const float4*)(qsrc + (size_t)row * QKV3 + c4 * 4);
            *(float4*)(sm + row * 68 + c4 * 4) = v;
        }
    }
    __syncthreads();
    float qreg[64];
    #pragma unroll
    for (int kk = 0; kk < 64; kk++) qreg[kk] = sm[r * 68 + kk];
    __syncthreads();

    float O[64];
    #pragma unroll
    for (int d = 0; d < 64; d++) O[d] = 0.f;
    float mrun = -INFINITY;
    float lrun = 0.f;

    const size_t mbase = ((size_t)bt * SEQ + q0) * SEQ;

    for (int kt = 0; kt < 8; kt++) {
        const int j0 = kt * 64;

        // K / V tiles (64x64 each), coalesced float4
        #pragma unroll
        for (int i = r; i < 1024; i += 128) {
            int jr = i >> 4;
            int c4 = i & 15;
            const float* kb = qkv_bt + (size_t)(j0 + jr) * QKV3 + EDIM + h * HD + c4 * 4;
            *(float4*)(Ks + jr * 64 + c4 * 4) = *(const float4*)kb;
            *(float4*)(Vs + jr * 64 + c4 * 4) = *(const float4*)(kb + EDIM);
        }
        // E tile = mask + edge, 128x64, stored with stride 65
        #pragma unroll
        for (int i = r; i < 2048; i += 128) {
            int row = i >> 4;
            int c4  = i & 15;
            size_t off = mbase + (size_t)row * SEQ + j0 + c4 * 4;
            float4 mv = *(const float4*)(mask + off);
            float4 ev = *(const float4*)(edge + off);
            float* ep = Es + row * 65 + c4 * 4;
            ep[0] = mv.x + ev.x;
            ep[1] = mv.y + ev.y;
            ep[2] = mv.z + ev.z;
            ep[3] = mv.w + ev.w;
        }
        __syncthreads();

        #pragma unroll
        for (int c = 0; c < 4; c++) {
            float s[16];
            #pragma unroll
            for (int jj = 0; jj < 16; jj++) {
                const int j = c * 16 + jj;
                const float* kr = Ks + j * 64;   // broadcast across the warp
                float a0 = 0.f, a1 = 0.f, a2 = 0.f, a3 = 0.f;
                #pragma unroll
                for (int kk = 0; kk < 64; kk += 4) {
                    a0 += qreg[kk]     * kr[kk];
                    a1 += qreg[kk + 1] * kr[kk + 1];
                    a2 += qreg[kk + 2] * kr[kk + 2];
                    a3 += qreg[kk + 3] * kr[kk + 3];
                }
                s[jj] = ((a0 + a1) + (a2 + a3)) * 0.125f + Es[r * 65 + j];
            }
            float mc = s[0];
            #pragma unroll
            for (int jj = 1; jj < 16; jj++) mc = fmaxf(mc, s[jj]);
            const float mnew  = fmaxf(mrun, mc);
            const float alpha = __expf(mrun - mnew);
            lrun *= alpha;
            #pragma unroll
            for (int d = 0; d < 64; d++) O[d] *= alpha;
            #pragma unroll
            for (int jj = 0; jj < 16; jj++) {
                const float p = __expf(s[jj] - mnew);
                lrun += p;
                const float* vr = Vs + (c * 16 + jj) * 64;  // broadcast
                #pragma unroll
                for (int d = 0; d < 64; d++) O[d] += p * vr[d];
            }
            mrun = mnew;
        }
        __syncthreads();
    }

    const float inv = 1.f / lrun;
    float* op = g_attn + ((size_t)(bt * SEQ) + q0 + r) * EDIM + h * HD;
    #pragma unroll
    for (int d = 0; d < 64; d += 4) {
        float4 v;
        v.x = O[d]     * inv;
        v.y = O[d + 1] * inv;
        v.z = O[d + 2] * inv;
        v.w = O[d + 3] * inv;
        *(float4*)(op + d) = v;
    }
}

// ---------------------------------------------------------------------------
// Launch: QKV GEMM -> attention -> proj GEMM
// Inputs (metadata order): hidden_states, edge_matrix, attention_mask,
//                          w_attn, b_attn, w_proj, b_proj, n_head
// ---------------------------------------------------------------------------
extern "C" void kernel_launch(void* const* d_in, const int* in_sizes, int n_in,
                              void* d_out, int out_size)
{
    const float* hidden = (const float*)d_in[0];
    const float* edge   = (const float*)d_in[1];
    const float* mask   = (const float*)d_in[2];
    const float* w_attn = (const float*)d_in[3];
    const float* b_attn = (const float*)d_in[4];
    const float* w_proj = (const float*)d_in[5];
    const float* b_proj = (const float*)d_in[6];
    (void)in_sizes; (void)n_in; (void)out_size;

    float *qkv_ptr, *attn_ptr;
    cudaGetSymbolAddress((void**)&qkv_ptr, g_qkv);
    cudaGetSymbolAddress((void**)&attn_ptr, g_attn);

    cudaFuncSetAttribute(attn_kernel,
                         cudaFuncAttributeMaxDynamicSharedMemorySize,
                         ATTN_SMEM_BYTES);

    dim3 g1(QKV3 / 128, MROWS / 128);
    sgemm_bias<<<g1, 256>>>(hidden, w_attn, b_attn, qkv_ptr, MROWS, QKV3, EDIM);

    dim3 ga(SEQ / 128, NH, BT_);
    attn_kernel<<<ga, 128, ATTN_SMEM_BYTES>>>(mask, edge);

    dim3 g2(EDIM / 128, MROWS / 128);
    sgemm_bias<<<g2, 256>>>(attn_ptr, w_proj, b_proj, (float*)d_out, MROWS, EDIM, EDIM);
}

// round 6
// speedup vs baseline: 1.3652x; 1.3652x over previous
#include <cuda_runtime.h>
#include <cuda_bf16.h>
#include <math.h>
#include <stdint.h>

#define BT_   16
#define SEQ   512
#define EDIM  768
#define NH    12
#define HD    64
#define QKV3  2304
#define MROWS (BT_*SEQ)   /* 8192 */

// ---------------------------------------------------------------------------
// Scratch (allocation-free, __device__ globals)
// ---------------------------------------------------------------------------
__device__ float g_qkv[(size_t)MROWS * QKV3];            // 75.5 MB
__device__ float g_attn[(size_t)MROWS * EDIM];           // 25 MB
__device__ __nv_bfloat16 g_Ahi[(size_t)MROWS * EDIM];    // 12.6 MB
__device__ __nv_bfloat16 g_Alo[(size_t)MROWS * EDIM];
__device__ __nv_bfloat16 g_Bhi[(size_t)QKV3 * EDIM];     // 3.5 MB
__device__ __nv_bfloat16 g_Blo[(size_t)QKV3 * EDIM];

// ---------------------------------------------------------------------------
// m16n8k16 bf16 mma (sm_80+ -- works on base sm_100 target, no 'a' needed)
// ---------------------------------------------------------------------------
#define MMA16816(d, a, b) \
    asm volatile("mma.sync.aligned.m16n8k16.row.col.f32.bf16.bf16.f32 " \
        "{%0,%1,%2,%3}, {%4,%5,%6,%7}, {%8,%9}, {%0,%1,%2,%3};" \
        : "+f"((d)[0]), "+f"((d)[1]), "+f"((d)[2]), "+f"((d)[3]) \
        : "r"((a)[0]), "r"((a)[1]), "r"((a)[2]), "r"((a)[3]), \
          "r"((b)[0]), "r"((b)[1]))

// ---------------------------------------------------------------------------
// fp32 -> (hi, lo) bf16 split, elementwise (n % 4 == 0)
// ---------------------------------------------------------------------------
__global__ __launch_bounds__(256)
void convert_split(const float* __restrict__ x, __nv_bfloat16* __restrict__ hi,
                   __nv_bfloat16* __restrict__ lo, int n4)
{
    int i = blockIdx.x * blockDim.x + threadIdx.x;
    if (i >= n4) return;
    float4 v = ((const float4*)x)[i];
    __nv_bfloat16 h0 = __float2bfloat16_rn(v.x);
    __nv_bfloat16 h1 = __float2bfloat16_rn(v.y);
    __nv_bfloat16 h2 = __float2bfloat16_rn(v.z);
    __nv_bfloat16 h3 = __float2bfloat16_rn(v.w);
    __nv_bfloat16 l0 = __float2bfloat16_rn(v.x - __bfloat162float(h0));
    __nv_bfloat16 l1 = __float2bfloat16_rn(v.y - __bfloat162float(h1));
    __nv_bfloat16 l2 = __float2bfloat16_rn(v.z - __bfloat162float(h2));
    __nv_bfloat16 l3 = __float2bfloat16_rn(v.w - __bfloat162float(h3));
    ((__nv_bfloat162*)hi)[2 * i]     = __nv_bfloat162(h0, h1);
    ((__nv_bfloat162*)hi)[2 * i + 1] = __nv_bfloat162(h2, h3);
    ((__nv_bfloat162*)lo)[2 * i]     = __nv_bfloat162(l0, l1);
    ((__nv_bfloat162*)lo)[2 * i + 1] = __nv_bfloat162(l2, l3);
}

// ---------------------------------------------------------------------------
// w[K][N] fp32 -> Wt_hi/lo[N][K] bf16 (tiled transpose + split)
// block (32, 8); grid (N/32, K/32)
// ---------------------------------------------------------------------------
__global__ __launch_bounds__(256)
void transpose_split(const float* __restrict__ w, __nv_bfloat16* __restrict__ hi,
                     __nv_bfloat16* __restrict__ lo, int K, int N)
{
    __shared__ float s[32][33];
    const int n0 = blockIdx.x * 32;
    const int k0 = blockIdx.y * 32;
    const int tx = threadIdx.x, ty = threadIdx.y;
    #pragma unroll
    for (int r = 0; r < 4; r++)
        s[ty + 8 * r][tx] = w[(size_t)(k0 + ty + 8 * r) * N + n0 + tx];
    __syncthreads();
    #pragma unroll
    for (int r = 0; r < 4; r++) {
        float v = s[tx][ty + 8 * r];
        int n = n0 + ty + 8 * r;
        __nv_bfloat16 h = __float2bfloat16_rn(v);
        __nv_bfloat16 l = __float2bfloat16_rn(v - __bfloat162float(h));
        hi[(size_t)n * K + k0 + tx] = h;
        lo[(size_t)n * K + k0 + tx] = l;
    }
}

// ---------------------------------------------------------------------------
// Tensor-core GEMM via mma.sync (split-bf16, 3 passes) + bias.
// C[M,N] = A[M,K] @ B^T  with A*: [M][K] bf16, B*: [N][K] bf16 (K contiguous).
// 128x128 tile, BK=32, 256 thr, 8 warps = 2(M)x4(N), warp tile 64x32.
// Smem stride 40 elements -> conflict-free fragment LDS.
// ---------------------------------------------------------------------------
#define SA 40

__global__ __launch_bounds__(256)
void gemm_mma(const __nv_bfloat16* __restrict__ Ahi, const __nv_bfloat16* __restrict__ Alo,
              const __nv_bfloat16* __restrict__ Bhi, const __nv_bfloat16* __restrict__ Blo,
              const float* __restrict__ bias, float* __restrict__ C,
              int M, int N, int K)
{
    __shared__ __nv_bfloat16 Ash[128 * SA];
    __shared__ __nv_bfloat16 Als[128 * SA];
    __shared__ __nv_bfloat16 Bsh[128 * SA];
    __shared__ __nv_bfloat16 Bls[128 * SA];

    const int tid = threadIdx.x;
    const int wid = tid >> 5;
    const int lid = tid & 31;
    const int wm  = (wid >> 2) * 64;   // warp row offset (0 / 64)
    const int wn  = (wid & 3) * 32;    // warp col offset (0/32/64/96)
    const int r   = lid >> 2;          // 0..7
    const int cq  = lid & 3;           // 0..3
    const int bn0 = blockIdx.x * 128;
    const int bm0 = blockIdx.y * 128;

    float acc[4][4][4];
    #pragma unroll
    for (int mi = 0; mi < 4; mi++)
        #pragma unroll
        for (int ni = 0; ni < 4; ni++)
            #pragma unroll
            for (int q = 0; q < 4; q++) acc[mi][ni][q] = 0.f;

    for (int k0 = 0; k0 < K; k0 += 32) {
        const __nv_bfloat16* pa = Ahi + (size_t)bm0 * K + k0;
        const __nv_bfloat16* pl = Alo + (size_t)bm0 * K + k0;
        const __nv_bfloat16* pb = Bhi + (size_t)bn0 * K + k0;
        const __nv_bfloat16* pc = Blo + (size_t)bn0 * K + k0;
        #pragma unroll
        for (int i = 0; i < 2; i++) {
            int u   = tid + (i << 8);        // 512 uint4 = 128 rows x 4
            int row = u >> 2;
            int c4  = u & 3;
            size_t go = (size_t)row * K + (c4 << 3);
            int so = row * SA + (c4 << 3);
            *(uint4*)&Ash[so] = *(const uint4*)(pa + go);
            *(uint4*)&Als[so] = *(const uint4*)(pl + go);
            *(uint4*)&Bsh[so] = *(const uint4*)(pb + go);
            *(uint4*)&Bls[so] = *(const uint4*)(pc + go);
        }
        __syncthreads();

        #pragma unroll
        for (int ks = 0; ks < 2; ks++) {
            const int kb = ks << 4;
            // A fragments (hi & lo): 4 m-atoms x 4 regs
            uint32_t ah[4][4], al[4][4];
            #pragma unroll
            for (int mi = 0; mi < 4; mi++) {
                int base = (wm + mi * 16 + r) * SA + kb + cq * 2;
                ah[mi][0] = *(const uint32_t*)&Ash[base];
                ah[mi][1] = *(const uint32_t*)&Ash[base + 8 * SA];
                ah[mi][2] = *(const uint32_t*)&Ash[base + 8];
                ah[mi][3] = *(const uint32_t*)&Ash[base + 8 * SA + 8];
                al[mi][0] = *(const uint32_t*)&Als[base];
                al[mi][1] = *(const uint32_t*)&Als[base + 8 * SA];
                al[mi][2] = *(const uint32_t*)&Als[base + 8];
                al[mi][3] = *(const uint32_t*)&Als[base + 8 * SA + 8];
            }
            // B fragments (hi & lo): 4 n-atoms x 2 regs
            uint32_t bh[4][2], bl[4][2];
            #pragma unroll
            for (int ni = 0; ni < 4; ni++) {
                int base = (wn + ni * 8 + r) * SA + kb + cq * 2;
                bh[ni][0] = *(const uint32_t*)&Bsh[base];
                bh[ni][1] = *(const uint32_t*)&Bsh[base + 8];
                bl[ni][0] = *(const uint32_t*)&Bls[base];
                bl[ni][1] = *(const uint32_t*)&Bls[base + 8];
            }
            // pass 1: hi x hi
            #pragma unroll
            for (int mi = 0; mi < 4; mi++)
                #pragma unroll
                for (int ni = 0; ni < 4; ni++)
                    MMA16816(acc[mi][ni], ah[mi], bh[ni]);
            // pass 2: lo x hi
            #pragma unroll
            for (int mi = 0; mi < 4; mi++)
                #pragma unroll
                for (int ni = 0; ni < 4; ni++)
                    MMA16816(acc[mi][ni], al[mi], bh[ni]);
            // pass 3: hi x lo
            #pragma unroll
            for (int mi = 0; mi < 4; mi++)
                #pragma unroll
                for (int ni = 0; ni < 4; ni++)
                    MMA16816(acc[mi][ni], ah[mi], bl[ni]);
        }
        __syncthreads();
    }

    // Epilogue: c0,c1 at (row, col..col+1); c2,c3 at (row+8, col..col+1)
    #pragma unroll
    for (int mi = 0; mi < 4; mi++) {
        int row = bm0 + wm + mi * 16 + r;
        #pragma unroll
        for (int ni = 0; ni < 4; ni++) {
            int col = bn0 + wn + ni * 8 + cq * 2;
            float b0 = bias[col], b1 = bias[col + 1];
            float2 v0 = make_float2(acc[mi][ni][0] + b0, acc[mi][ni][1] + b1);
            float2 v1 = make_float2(acc[mi][ni][2] + b0, acc[mi][ni][3] + b1);
            *(float2*)(C + (size_t)row * N + col)       = v0;
            *(float2*)(C + (size_t)(row + 8) * N + col) = v1;
        }
    }
}

// ---------------------------------------------------------------------------
// Flash-style attention (unchanged from round 1 -- passed; next round's target)
// ---------------------------------------------------------------------------
#define ATTN_SMEM_FLOATS 16512
#define ATTN_SMEM_BYTES  (ATTN_SMEM_FLOATS * 4)

__global__ __launch_bounds__(128)
void attn_kernel(const float* __restrict__ mask, const float* __restrict__ edge)
{
    extern __shared__ float smf[];
    float* Ks = smf;
    float* Vs = smf + 4096;
    float* Es = smf + 8192;

    const int r  = threadIdx.x;
    const int q0 = blockIdx.x * 128;
    const int h  = blockIdx.y;
    const int bt = blockIdx.z;

    const float* qkv_bt = g_qkv + (size_t)bt * SEQ * QKV3;

    {
        const float* qsrc = qkv_bt + (size_t)q0 * QKV3 + h * HD;
        #pragma unroll
        for (int i = r; i < 2048; i += 128) {
            int row = i >> 4;
            int c4  = i & 15;
            float4 v = *(const float4*)(qsrc + (size_t)row * QKV3 + c4 * 4);
            *(float4*)(smf + row * 68 + c4 * 4) = v;
        }
    }
    __syncthreads();
    float qreg[64];
    #pragma unroll
    for (int kk = 0; kk < 64; kk++) qreg[kk] = smf[r * 68 + kk];
    __syncthreads();

    float O[64];
    #pragma unroll
    for (int d = 0; d < 64; d++) O[d] = 0.f;
    float mrun = -INFINITY;
    float lrun = 0.f;

    const size_t mbase = ((size_t)bt * SEQ + q0) * SEQ;

    for (int kt = 0; kt < 8; kt++) {
        const int j0 = kt * 64;
        #pragma unroll
        for (int i = r; i < 1024; i += 128) {
            int jr = i >> 4;
            int c4 = i & 15;
            const float* kb = qkv_bt + (size_t)(j0 + jr) * QKV3 + EDIM + h * HD + c4 * 4;
            *(float4*)(Ks + jr * 64 + c4 * 4) = *(const float4*)kb;
            *(float4*)(Vs + jr * 64 + c4 * 4) = *(const float4*)(kb + EDIM);
        }
        #pragma unroll
        for (int i = r; i < 2048; i += 128) {
            int row = i >> 4;
            int c4  = i & 15;
            size_t off = mbase + (size_t)row * SEQ + j0 + c4 * 4;
            float4 mv = *(const float4*)(mask + off);
            float4 ev = *(const float4*)(edge + off);
            float* ep = Es + row * 65 + c4 * 4;
            ep[0] = mv.x + ev.x;
            ep[1] = mv.y + ev.y;
            ep[2] = mv.z + ev.z;
            ep[3] = mv.w + ev.w;
        }
        __syncthreads();

        #pragma unroll
        for (int c = 0; c < 4; c++) {
            float s[16];
            #pragma unroll
            for (int jj = 0; jj < 16; jj++) {
                const int j = c * 16 + jj;
                const float* kr = Ks + j * 64;
                float a0 = 0.f, a1 = 0.f, a2 = 0.f, a3 = 0.f;
                #pragma unroll
                for (int kk = 0; kk < 64; kk += 4) {
                    a0 += qreg[kk]     * kr[kk];
                    a1 += qreg[kk + 1] * kr[kk + 1];
                    a2 += qreg[kk + 2] * kr[kk + 2];
                    a3 += qreg[kk + 3] * kr[kk + 3];
                }
                s[jj] = ((a0 + a1) + (a2 + a3)) * 0.125f + Es[r * 65 + j];
            }
            float mc = s[0];
            #pragma unroll
            for (int jj = 1; jj < 16; jj++) mc = fmaxf(mc, s[jj]);
            const float mnew  = fmaxf(mrun, mc);
            const float alpha = __expf(mrun - mnew);
            lrun *= alpha;
            #pragma unroll
            for (int d = 0; d < 64; d++) O[d] *= alpha;
            #pragma unroll
            for (int jj = 0; jj < 16; jj++) {
                const float p = __expf(s[jj] - mnew);
                lrun += p;
                const float* vr = Vs + (c * 16 + jj) * 64;
                #pragma unroll
                for (int d = 0; d < 64; d++) O[d] += p * vr[d];
            }
            mrun = mnew;
        }
        __syncthreads();
    }

    const float inv = 1.f / lrun;
    float* op = g_attn + ((size_t)(bt * SEQ) + q0 + r) * EDIM + h * HD;
    #pragma unroll
    for (int d = 0; d < 64; d += 4) {
        float4 v;
        v.x = O[d]     * inv;
        v.y = O[d + 1] * inv;
        v.z = O[d + 2] * inv;
        v.w = O[d + 3] * inv;
        *(float4*)(op + d) = v;
    }
}

// ---------------------------------------------------------------------------
// Launch pipeline
// ---------------------------------------------------------------------------
extern "C" void kernel_launch(void* const* d_in, const int* in_sizes, int n_in,
                              void* d_out, int out_size)
{
    const float* hidden = (const float*)d_in[0];
    const float* edge   = (const float*)d_in[1];
    const float* mask   = (const float*)d_in[2];
    const float* w_attn = (const float*)d_in[3];
    const float* b_attn = (const float*)d_in[4];
    const float* w_proj = (const float*)d_in[5];
    const float* b_proj = (const float*)d_in[6];
    (void)in_sizes; (void)n_in; (void)out_size;

    float *qkv_ptr, *attn_ptr;
    __nv_bfloat16 *ahi, *alo, *bhi, *blo;
    cudaGetSymbolAddress((void**)&qkv_ptr, g_qkv);
    cudaGetSymbolAddress((void**)&attn_ptr, g_attn);
    cudaGetSymbolAddress((void**)&ahi, g_Ahi);
    cudaGetSymbolAddress((void**)&alo, g_Alo);
    cudaGetSymbolAddress((void**)&bhi, g_Bhi);
    cudaGetSymbolAddress((void**)&blo, g_Blo);

    cudaFuncSetAttribute(attn_kernel, cudaFuncAttributeMaxDynamicSharedMemorySize,
                         ATTN_SMEM_BYTES);

    const int nA4 = (MROWS * EDIM) / 4;

    // QKV = hidden @ w_attn + b_attn
    convert_split<<<(nA4 + 255) / 256, 256>>>(hidden, ahi, alo, nA4);
    transpose_split<<<dim3(QKV3 / 32, EDIM / 32), dim3(32, 8)>>>(w_attn, bhi, blo, EDIM, QKV3);
    gemm_mma<<<dim3(QKV3 / 128, MROWS / 128), 256>>>(
        ahi, alo, bhi, blo, b_attn, qkv_ptr, MROWS, QKV3, EDIM);

    // Attention
    attn_kernel<<<dim3(SEQ / 128, NH, BT_), 128, ATTN_SMEM_BYTES>>>(mask, edge);

    // Out = attn @ w_proj + b_proj
    convert_split<<<(nA4 + 255) / 256, 256>>>(attn_ptr, ahi, alo, nA4);
    transpose_split<<<dim3(EDIM / 32, EDIM / 32), dim3(32, 8)>>>(w_proj, bhi, blo, EDIM, EDIM);
    gemm_mma<<<dim3(EDIM / 128, MROWS / 128), 256>>>(
        ahi, alo, bhi, blo, b_proj, (float*)d_out, MROWS, EDIM, EDIM);
}